// round 16
// baseline (speedup 1.0000x reference)
#include <cuda_runtime.h>
#include <cuda_fp16.h>

// SilkNNUE: out[r] = MLP( relu( sum_{k<29} emb[x[r,k]] ) )
// R15: occupancy/MLP push on the R14 HMMA design.
//  - h stored as SINGLE fp16 (hL dropped): smem 55.8 -> 37.5 KB
//  - launch_bounds(256,5): 5 CTAs/SM (40 warps, was 27)
//  - gather k-loop unroll x2: 8 LDG.128 in flight per warp
//  - w2 keeps hi/lo split (2 MMAs/tile); layer3 A hi/lo in-register as before

#define VOCAB 14848
#define EMBD  128
#define WARPS_PER_BLOCK 8
#define ROWS_PER_WARP   8
#define ROWS_PER_BLOCK  (WARPS_PER_BLOCK * ROWS_PER_WARP)
#define FULLMASK 0xffffffffu
#define HSTRIDE 136   // halves per h row (128 + 8 pad: conflict-free A-frag LDS)

typedef unsigned long long ull;

__device__ __half g_embh[VOCAB * EMBD];   // 3.8 MB static scratch

// ---- pre-pass: fp32 emb -> fp16 table ----
__global__ __launch_bounds__(256) void convert_emb_kernel(const float* __restrict__ emb)
{
    const int i = blockIdx.x * 256 + threadIdx.x;       // one per 8 elements
    const float4* p = (const float4*)emb + (size_t)i * 2;
    const float4 a = p[0], b = p[1];
    __half2 h0 = __floats2half2_rn(a.x, a.y);
    __half2 h1 = __floats2half2_rn(a.z, a.w);
    __half2 h2 = __floats2half2_rn(b.x, b.y);
    __half2 h3 = __floats2half2_rn(b.z, b.w);
    uint4 o;
    o.x = *(unsigned*)&h0; o.y = *(unsigned*)&h1;
    o.z = *(unsigned*)&h2; o.w = *(unsigned*)&h3;
    ((uint4*)g_embh)[i] = o;
}

// ---- packed fp32x2 helpers ----
__device__ __forceinline__ ull pack2(float x, float y)
{
    ull v; asm("mov.b64 %0, {%1, %2};" : "=l"(v) : "f"(x), "f"(y)); return v;
}
__device__ __forceinline__ void fadd2(ull& acc, float x, float y)
{
    ull v = pack2(x, y);
    asm("add.rn.f32x2 %0, %0, %1;" : "+l"(acc) : "l"(v));
}
__device__ __forceinline__ float2 unpack2(ull acc)
{
    float2 f; asm("mov.b64 {%0, %1}, %2;" : "=f"(f.x), "=f"(f.y) : "l"(acc)); return f;
}
__device__ __forceinline__ __half2 u2h2(unsigned v) { return *(__half2*)&v; }
__device__ __forceinline__ unsigned h2u(__half2 h)  { return *(unsigned*)&h; }

// m16n8k16 fp16 MMA (row.col), fp32 accum, C in-place
__device__ __forceinline__ void mma16816(float* c,
    unsigned a0, unsigned a1, unsigned a2, unsigned a3, unsigned b0, unsigned b1)
{
    asm volatile(
        "mma.sync.aligned.m16n8k16.row.col.f32.f16.f16.f32 "
        "{%0,%1,%2,%3}, {%4,%5,%6,%7}, {%8,%9}, {%0,%1,%2,%3};"
        : "+f"(c[0]), "+f"(c[1]), "+f"(c[2]), "+f"(c[3])
        : "r"(a0), "r"(a1), "r"(a2), "r"(a3), "r"(b0), "r"(b1));
}

// split a float pair into fp16 hi + fp16 residual
__device__ __forceinline__ void split2(float x, float y, unsigned& hiu, unsigned& lou)
{
    __half2 hh = __floats2half2_rn(x, y);
    float2 bk = __half22float2(hh);
    __half2 ll = __floats2half2_rn(x - bk.x, y - bk.y);
    hiu = h2u(hh); lou = h2u(ll);
}

struct Smem {
    __half hH[ROWS_PER_BLOCK][HSTRIDE];     // 17408 B: h fp16
    uint2  w2fH[8][4][32];                  // 8192 B: w2 B-fragments hi [kb][nb][lane]
    uint2  w2fL[8][4][32];                  // 8192 B: w2 B-fragments lo
    uint2  w3f [4][4][32];                  // 4096 B: w3 B-fragments [kb2][nb][lane]
    float  b2s[32], b3s[32], w4s[64];       // 512 B
};                                           // total 37.5 KB -> 5 CTAs/SM

extern __shared__ __align__(16) char smem_raw[];

__global__ __launch_bounds__(256, 5) void silk_nnue_kernel(
    const int*   __restrict__ x,     // (nrows, 32) int32, first 29 cols used
    const float* __restrict__ w2,    // (32, 128)
    const float* __restrict__ b2,    // (32,)
    const float* __restrict__ w3,    // (32, 64)
    const float* __restrict__ b3,    // (32,)
    const float* __restrict__ w4,    // (1, 64)
    float*       __restrict__ out,   // (nrows,)
    int nrows)
{
    Smem* S = (Smem*)smem_raw;
    const int tid = threadIdx.x;

    // ---- prologue: fragment-ordered weight tables ----
    // B frag (k16 x n8, col-major): b0,b1 = B[k0,k0+1][n], b2,b3 = B[k0+8,k0+9][n];
    // n = nb*8 + t/4, k0 = kb*16 + 2*(t%4). Layer2 B[k][n] = w2[n][k].
    for (int e = tid; e < 8 * 4 * 32; e += 256) {
        const int t = e & 31, nb = (e >> 5) & 3, kb = e >> 7;
        const int n = nb * 8 + (t >> 2), k0 = kb * 16 + 2 * (t & 3);
        const float* wp = w2 + n * 128 + k0;
        unsigned hA, lA, hB, lB;
        split2(wp[0], wp[1], hA, lA);
        split2(wp[8], wp[9], hB, lB);
        S->w2fH[kb][nb][t] = make_uint2(hA, hB);
        S->w2fL[kb][nb][t] = make_uint2(lA, lB);
    }
    // Layer3 B[m][i] = w3[i][m] (m = CReLU feature, i = output), fp16 single.
    for (int e = tid; e < 4 * 4 * 32; e += 256) {
        const int t = e & 31, nb = (e >> 5) & 3, kb2 = e >> 7;
        const int i = nb * 8 + (t >> 2), m0 = kb2 * 16 + 2 * (t & 3);
        const float* wp = w3 + i * 64 + m0;
        S->w3f[kb2][nb][t] = make_uint2(
            h2u(__floats2half2_rn(wp[0], wp[1])),
            h2u(__floats2half2_rn(wp[8], wp[9])));
    }
    if (tid < 32) { S->b2s[tid] = b2[tid]; S->b3s[tid] = b3[tid]; }
    if (tid < 64) { S->w4s[tid] = w4[tid]; }
    __syncthreads();

    const int warp = tid >> 5;
    const int lane = tid & 31;
    const int row0 = blockIdx.x * ROWS_PER_BLOCK + warp * ROWS_PER_WARP;
    if (row0 >= nrows) return;          // warp-uniform
    const int rlast = nrows - 1;

    const int sub = lane & 15;          // 16B chunk within a 256B fp16 emb row
    const int hi  = lane >> 4;          // which row of a pair this lane gathers

    // ---- index prefetch: pair indices packed 16+16 (VOCAB < 65536) ----
    unsigned myidxp[4];
    #pragma unroll
    for (int p = 0; p < 4; p++) {
        const int ra = min(row0 + 2 * p,     rlast);
        const int rb = min(row0 + 2 * p + 1, rlast);
        myidxp[p] = (unsigned)x[ra * 32 + lane] | ((unsigned)x[rb * 32 + lane] << 16);
    }

    const __half* __restrict__ embh = g_embh;
    const int sel_sh = hi << 4;

    // ---- gather-sum, two passes of 2 row-pairs; HADD2 pre-add; unroll x2 ----
    #pragma unroll
    for (int ph = 0; ph < 2; ph++) {
        ull acc[2][4];
        #pragma unroll
        for (int p2 = 0; p2 < 2; p2++)
            #pragma unroll
            for (int q = 0; q < 4; q++) acc[p2][q] = 0ull;

        #pragma unroll 2
        for (int k = 0; k < 28; k += 2) {
            #pragma unroll
            for (int p2 = 0; p2 < 2; p2++) {
                const unsigned pk0 = __shfl_sync(FULLMASK, myidxp[ph * 2 + p2], k);
                const unsigned pk1 = __shfl_sync(FULLMASK, myidxp[ph * 2 + p2], k + 1);
                const int i0 = (int)((pk0 >> sel_sh) & 0xffffu);
                const int i1 = (int)((pk1 >> sel_sh) & 0xffffu);
                const uint4 v0 = *(const uint4*)(embh + (size_t)i0 * EMBD + sub * 8);
                const uint4 v1 = *(const uint4*)(embh + (size_t)i1 * EMBD + sub * 8);
                const __half2 s0 = __hadd2(u2h2(v0.x), u2h2(v1.x));
                const __half2 s1 = __hadd2(u2h2(v0.y), u2h2(v1.y));
                const __half2 s2 = __hadd2(u2h2(v0.z), u2h2(v1.z));
                const __half2 s3 = __hadd2(u2h2(v0.w), u2h2(v1.w));
                float2 f;
                f = __half22float2(s0); fadd2(acc[p2][0], f.x, f.y);
                f = __half22float2(s1); fadd2(acc[p2][1], f.x, f.y);
                f = __half22float2(s2); fadd2(acc[p2][2], f.x, f.y);
                f = __half22float2(s3); fadd2(acc[p2][3], f.x, f.y);
            }
        }
        #pragma unroll
        for (int p2 = 0; p2 < 2; p2++) {              // leftover k = 28
            const unsigned pk = __shfl_sync(FULLMASK, myidxp[ph * 2 + p2], 28);
            const int idx = (int)((pk >> sel_sh) & 0xffffu);
            const uint4 v = *(const uint4*)(embh + (size_t)idx * EMBD + sub * 8);
            float2 f;
            f = __half22float2(u2h2(v.x)); fadd2(acc[p2][0], f.x, f.y);
            f = __half22float2(u2h2(v.y)); fadd2(acc[p2][1], f.x, f.y);
            f = __half22float2(u2h2(v.z)); fadd2(acc[p2][2], f.x, f.y);
            f = __half22float2(u2h2(v.w)); fadd2(acc[p2][3], f.x, f.y);
        }

        // ReLU + single-fp16 stage (lane owns [sub*8, sub*8+8) of row 2p+hi)
        #pragma unroll
        for (int p2 = 0; p2 < 2; p2++) {
            const int row = 2 * (ph * 2 + p2) + hi;
            const float2 f0 = unpack2(acc[p2][0]);
            const float2 f1 = unpack2(acc[p2][1]);
            const float2 f2 = unpack2(acc[p2][2]);
            const float2 f3 = unpack2(acc[p2][3]);
            uint4 sH;
            sH.x = h2u(__floats2half2_rn(fmaxf(f0.x, 0.f), fmaxf(f0.y, 0.f)));
            sH.y = h2u(__floats2half2_rn(fmaxf(f1.x, 0.f), fmaxf(f1.y, 0.f)));
            sH.z = h2u(__floats2half2_rn(fmaxf(f2.x, 0.f), fmaxf(f2.y, 0.f)));
            sH.w = h2u(__floats2half2_rn(fmaxf(f3.x, 0.f), fmaxf(f3.y, 0.f)));
            *(uint4*)&S->hH[warp * 8 + row][sub * 8] = sH;
        }
    }
    __syncwarp();

    // ---- layer 2: MMA. A frag: row = lane/4 (dup rows 8-15), k0 = 2*(lane&3) ----
    float c[4][4];
    #pragma unroll
    for (int nb = 0; nb < 4; nb++)
        #pragma unroll
        for (int q = 0; q < 4; q++) c[nb][q] = 0.f;

    const int rA = warp * 8 + (lane >> 2);
    const int kc = 2 * (lane & 3);
    #pragma unroll
    for (int kb = 0; kb < 8; kb++) {
        const unsigned aH0 = *(const unsigned*)&S->hH[rA][kb * 16 + kc];
        const unsigned aH4 = *(const unsigned*)&S->hH[rA][kb * 16 + kc + 8];
        #pragma unroll
        for (int nb = 0; nb < 4; nb++) {
            const uint2 bH = S->w2fH[kb][nb][lane];
            const uint2 bL = S->w2fL[kb][nb][lane];
            mma16816(c[nb], aH0, aH0, aH4, aH4, bH.x, bH.y);  // h * w_hi
            mma16816(c[nb], aH0, aH0, aH4, aH4, bL.x, bL.y);  // h * w_lo
        }
    }
    // bias: thread holds o2[r=lane/4][j=nb*8+2*(lane&3)+{0,1}] in c[nb][0..1]
    const int jc = 2 * (lane & 3);
    #pragma unroll
    for (int nb = 0; nb < 4; nb++) {
        const float2 bb = *(const float2*)&S->b2s[nb * 8 + jc];
        c[nb][0] += bb.x; c[nb][1] += bb.y;
    }

    // ---- layer 3: A frags built in-register from c via CReLU (hi/lo split) ----
    float d[4][4];
    #pragma unroll
    for (int nb = 0; nb < 4; nb++)
        #pragma unroll
        for (int q = 0; q < 4; q++) d[nb][q] = 0.f;

    #pragma unroll
    for (int kb2 = 0; kb2 < 4; kb2++) {
        const int s0 = (kb2 & 1) * 2, s1 = s0 + 1;
        const float sg = (kb2 < 2) ? 1.f : -1.f;
        const float p0 = fmaxf(sg * c[s0][0], 0.f), p1 = fmaxf(sg * c[s0][1], 0.f);
        const float q0 = fmaxf(sg * c[s1][0], 0.f), q1 = fmaxf(sg * c[s1][1], 0.f);
        unsigned aH0, aL0, aH4, aL4;
        split2(p0, p1, aH0, aL0);
        split2(q0, q1, aH4, aL4);
        #pragma unroll
        for (int nb = 0; nb < 4; nb++) {
            const uint2 b = S->w3f[kb2][nb][lane];
            mma16816(d[nb], aH0, aH0, aH4, aH4, b.x, b.y);
            mma16816(d[nb], aL0, aL0, aL4, aL4, b.x, b.y);
        }
    }

    // ---- layer 4: CReLU dot + quad reduction ----
    float g = 0.f;
    #pragma unroll
    for (int nb = 0; nb < 4; nb++) {
        const float2 b3p = *(const float2*)&S->b3s[nb * 8 + jc];
        const float2 w4p = *(const float2*)&S->w4s[nb * 8 + jc];
        const float2 w4n = *(const float2*)&S->w4s[32 + nb * 8 + jc];
        const float oa = d[nb][0] + b3p.x;
        const float ob = d[nb][1] + b3p.y;
        g += fmaxf(oa, 0.f) * w4p.x + fmaxf(-oa, 0.f) * w4n.x;
        g += fmaxf(ob, 0.f) * w4p.y + fmaxf(-ob, 0.f) * w4n.y;
    }
    g += __shfl_xor_sync(FULLMASK, g, 1);
    g += __shfl_xor_sync(FULLMASK, g, 2);
    if ((lane & 3) == 0) {
        const int row = row0 + (lane >> 2);
        if (row < nrows) out[row] = g;
    }
}

extern "C" void kernel_launch(void* const* d_in, const int* in_sizes, int n_in,
                              void* d_out, int out_size)
{
    const int*   x   = (const int*)  d_in[0];
    const float* emb = (const float*)d_in[1];
    const float* w2  = (const float*)d_in[2];
    const float* b2  = (const float*)d_in[3];
    const float* w3  = (const float*)d_in[4];
    const float* b3  = (const float*)d_in[5];
    const float* w4  = (const float*)d_in[6];
    float* out = (float*)d_out;

    convert_emb_kernel<<<(VOCAB * EMBD / 8 + 255) / 256, 256>>>(emb);

    const int smem_bytes = (int)sizeof(Smem);
    cudaFuncSetAttribute(silk_nnue_kernel,
                         cudaFuncAttributeMaxDynamicSharedMemorySize, smem_bytes);

    const int nrows  = in_sizes[0] / 32;
    const int blocks = (nrows + ROWS_PER_BLOCK - 1) / ROWS_PER_BLOCK;
    silk_nnue_kernel<<<blocks, 256, smem_bytes>>>(x, w2, b2, w3, b3, w4, out, nrows);
}

// round 17
// speedup vs baseline: 1.0901x; 1.0901x over previous
#include <cuda_runtime.h>
#include <cuda_fp16.h>

// SilkNNUE: out[r] = MLP( relu( sum_{k<29} emb[x[r,k]] ) )
// R16: kernel is at ~85% of the practical LTS (L2) ceiling; occupancy is
// irrelevant (R14 vs R15 equal). Shave non-gather overhead:
//  - weight fragment tables + biases prebuilt in the pre-pass (block 0)
//  - main kernel reads weights from global (uniform -> L1-resident), no
//    weight smem, no per-CTA prologue, no prologue syncthreads
//  - smem = h staging only (17.4 KB static)

#define VOCAB 14848
#define EMBD  128
#define WARPS_PER_BLOCK 8
#define ROWS_PER_WARP   8
#define ROWS_PER_BLOCK  (WARPS_PER_BLOCK * ROWS_PER_WARP)
#define FULLMASK 0xffffffffu
#define HSTRIDE 136   // halves per h row (128 + 8 pad: conflict-free A-frag LDS)

typedef unsigned long long ull;

__device__ __half g_embh[VOCAB * EMBD];   // 3.8 MB fp16 table
__device__ uint2  g_w2fH[8][4][32];       // w2 B-fragments hi [kb][nb][lane]
__device__ uint2  g_w2fL[8][4][32];       // w2 B-fragments lo
__device__ uint2  g_w3f [4][4][32];       // w3 B-fragments [kb2][nb][lane]
__device__ float  g_b2s[32], g_b3s[32], g_w4s[64];

__device__ __forceinline__ __half2 u2h2(unsigned v) { return *(__half2*)&v; }
__device__ __forceinline__ unsigned h2u(__half2 h)  { return *(unsigned*)&h; }

// split a float pair into fp16 hi + fp16 residual
__device__ __forceinline__ void split2(float x, float y, unsigned& hiu, unsigned& lou)
{
    __half2 hh = __floats2half2_rn(x, y);
    float2 bk = __half22float2(hh);
    __half2 ll = __floats2half2_rn(x - bk.x, y - bk.y);
    hiu = h2u(hh); lou = h2u(ll);
}

// ---- pre-pass: fp32 emb -> fp16 table; block 0 also builds weight tables ----
__global__ __launch_bounds__(256) void convert_emb_kernel(
    const float* __restrict__ emb,
    const float* __restrict__ w2, const float* __restrict__ b2,
    const float* __restrict__ w3, const float* __restrict__ b3,
    const float* __restrict__ w4)
{
    const int i = blockIdx.x * 256 + threadIdx.x;       // one per 8 elements
    const float4* p = (const float4*)emb + (size_t)i * 2;
    const float4 a = p[0], b = p[1];
    __half2 h0 = __floats2half2_rn(a.x, a.y);
    __half2 h1 = __floats2half2_rn(a.z, a.w);
    __half2 h2 = __floats2half2_rn(b.x, b.y);
    __half2 h3 = __floats2half2_rn(b.z, b.w);
    uint4 o;
    o.x = *(unsigned*)&h0; o.y = *(unsigned*)&h1;
    o.z = *(unsigned*)&h2; o.w = *(unsigned*)&h3;
    ((uint4*)g_embh)[i] = o;

    if (blockIdx.x == 0) {
        const int tid = threadIdx.x;
        // B frag (k16 x n8, col-major): b0,b1 = B[k0,k0+1][n], b2,b3 = B[k0+8,k0+9][n]
        // n = nb*8 + t/4, k0 = kb*16 + 2*(t%4). Layer2 B[k][n] = w2[n][k].
        for (int e = tid; e < 8 * 4 * 32; e += 256) {
            const int t = e & 31, nb = (e >> 5) & 3, kb = e >> 7;
            const int n = nb * 8 + (t >> 2), k0 = kb * 16 + 2 * (t & 3);
            const float* wp = w2 + n * 128 + k0;
            unsigned hA, lA, hB, lB;
            split2(wp[0], wp[1], hA, lA);
            split2(wp[8], wp[9], hB, lB);
            g_w2fH[kb][nb][t] = make_uint2(hA, hB);
            g_w2fL[kb][nb][t] = make_uint2(lA, lB);
        }
        // Layer3 B[m][i] = w3[i][m], fp16 single (in error budget since R12)
        for (int e = tid; e < 4 * 4 * 32; e += 256) {
            const int t = e & 31, nb = (e >> 5) & 3, kb2 = e >> 7;
            const int ii = nb * 8 + (t >> 2), m0 = kb2 * 16 + 2 * (t & 3);
            const float* wp = w3 + ii * 64 + m0;
            g_w3f[kb2][nb][t] = make_uint2(
                h2u(__floats2half2_rn(wp[0], wp[1])),
                h2u(__floats2half2_rn(wp[8], wp[9])));
        }
        if (tid < 32) { g_b2s[tid] = b2[tid]; g_b3s[tid] = b3[tid]; }
        if (tid < 64) { g_w4s[tid] = w4[tid]; }
    }
}

// ---- packed fp32x2 helpers ----
__device__ __forceinline__ ull pack2(float x, float y)
{
    ull v; asm("mov.b64 %0, {%1, %2};" : "=l"(v) : "f"(x), "f"(y)); return v;
}
__device__ __forceinline__ void fadd2(ull& acc, float x, float y)
{
    ull v = pack2(x, y);
    asm("add.rn.f32x2 %0, %0, %1;" : "+l"(acc) : "l"(v));
}
__device__ __forceinline__ float2 unpack2(ull acc)
{
    float2 f; asm("mov.b64 {%0, %1}, %2;" : "=f"(f.x), "=f"(f.y) : "l"(acc)); return f;
}

// m16n8k16 fp16 MMA (row.col), fp32 accum, C in-place
__device__ __forceinline__ void mma16816(float* c,
    unsigned a0, unsigned a1, unsigned a2, unsigned a3, unsigned b0, unsigned b1)
{
    asm volatile(
        "mma.sync.aligned.m16n8k16.row.col.f32.f16.f16.f32 "
        "{%0,%1,%2,%3}, {%4,%5,%6,%7}, {%8,%9}, {%0,%1,%2,%3};"
        : "+f"(c[0]), "+f"(c[1]), "+f"(c[2]), "+f"(c[3])
        : "r"(a0), "r"(a1), "r"(a2), "r"(a3), "r"(b0), "r"(b1));
}

__global__ __launch_bounds__(256, 5) void silk_nnue_kernel(
    const int* __restrict__ x,       // (nrows, 32) int32, first 29 cols used
    float*     __restrict__ out,     // (nrows,)
    int nrows)
{
    __shared__ __align__(16) __half hH[ROWS_PER_BLOCK][HSTRIDE];   // 17408 B

    const int tid  = threadIdx.x;
    const int warp = tid >> 5;
    const int lane = tid & 31;
    const int row0 = blockIdx.x * ROWS_PER_BLOCK + warp * ROWS_PER_WARP;
    if (row0 >= nrows) return;          // warp-uniform
    const int rlast = nrows - 1;

    const int sub = lane & 15;          // 16B chunk within a 256B fp16 emb row
    const int hi  = lane >> 4;          // which row of a pair this lane gathers

    // ---- index prefetch: pair indices packed 16+16 (VOCAB < 65536) ----
    unsigned myidxp[4];
    #pragma unroll
    for (int p = 0; p < 4; p++) {
        const int ra = min(row0 + 2 * p,     rlast);
        const int rb = min(row0 + 2 * p + 1, rlast);
        myidxp[p] = (unsigned)x[ra * 32 + lane] | ((unsigned)x[rb * 32 + lane] << 16);
    }

    const __half* __restrict__ embh = g_embh;
    const int sel_sh = hi << 4;

    // ---- gather-sum, two passes of 2 row-pairs; HADD2 pre-add; unroll x2 ----
    #pragma unroll
    for (int ph = 0; ph < 2; ph++) {
        ull acc[2][4];
        #pragma unroll
        for (int p2 = 0; p2 < 2; p2++)
            #pragma unroll
            for (int q = 0; q < 4; q++) acc[p2][q] = 0ull;

        #pragma unroll 2
        for (int k = 0; k < 28; k += 2) {
            #pragma unroll
            for (int p2 = 0; p2 < 2; p2++) {
                const unsigned pk0 = __shfl_sync(FULLMASK, myidxp[ph * 2 + p2], k);
                const unsigned pk1 = __shfl_sync(FULLMASK, myidxp[ph * 2 + p2], k + 1);
                const int i0 = (int)((pk0 >> sel_sh) & 0xffffu);
                const int i1 = (int)((pk1 >> sel_sh) & 0xffffu);
                const uint4 v0 = *(const uint4*)(embh + (size_t)i0 * EMBD + sub * 8);
                const uint4 v1 = *(const uint4*)(embh + (size_t)i1 * EMBD + sub * 8);
                const __half2 s0 = __hadd2(u2h2(v0.x), u2h2(v1.x));
                const __half2 s1 = __hadd2(u2h2(v0.y), u2h2(v1.y));
                const __half2 s2 = __hadd2(u2h2(v0.z), u2h2(v1.z));
                const __half2 s3 = __hadd2(u2h2(v0.w), u2h2(v1.w));
                float2 f;
                f = __half22float2(s0); fadd2(acc[p2][0], f.x, f.y);
                f = __half22float2(s1); fadd2(acc[p2][1], f.x, f.y);
                f = __half22float2(s2); fadd2(acc[p2][2], f.x, f.y);
                f = __half22float2(s3); fadd2(acc[p2][3], f.x, f.y);
            }
        }
        #pragma unroll
        for (int p2 = 0; p2 < 2; p2++) {              // leftover k = 28
            const unsigned pk = __shfl_sync(FULLMASK, myidxp[ph * 2 + p2], 28);
            const int idx = (int)((pk >> sel_sh) & 0xffffu);
            const uint4 v = *(const uint4*)(embh + (size_t)idx * EMBD + sub * 8);
            float2 f;
            f = __half22float2(u2h2(v.x)); fadd2(acc[p2][0], f.x, f.y);
            f = __half22float2(u2h2(v.y)); fadd2(acc[p2][1], f.x, f.y);
            f = __half22float2(u2h2(v.z)); fadd2(acc[p2][2], f.x, f.y);
            f = __half22float2(u2h2(v.w)); fadd2(acc[p2][3], f.x, f.y);
        }

        // ReLU + single-fp16 stage (lane owns [sub*8, sub*8+8) of row 2p+hi)
        #pragma unroll
        for (int p2 = 0; p2 < 2; p2++) {
            const int row = 2 * (ph * 2 + p2) + hi;
            const float2 f0 = unpack2(acc[p2][0]);
            const float2 f1 = unpack2(acc[p2][1]);
            const float2 f2 = unpack2(acc[p2][2]);
            const float2 f3 = unpack2(acc[p2][3]);
            uint4 sH;
            sH.x = h2u(__floats2half2_rn(fmaxf(f0.x, 0.f), fmaxf(f0.y, 0.f)));
            sH.y = h2u(__floats2half2_rn(fmaxf(f1.x, 0.f), fmaxf(f1.y, 0.f)));
            sH.z = h2u(__floats2half2_rn(fmaxf(f2.x, 0.f), fmaxf(f2.y, 0.f)));
            sH.w = h2u(__floats2half2_rn(fmaxf(f3.x, 0.f), fmaxf(f3.y, 0.f)));
            *(uint4*)&hH[warp * 8 + row][sub * 8] = sH;
        }
    }
    __syncwarp();

    // ---- layer 2: MMA. A frag: row = lane/4 (dup rows 8-15), k0 = 2*(lane&3) ----
    // Weights from __device__ globals: uniform across warps/CTAs -> L1-resident.
    float c[4][4];
    #pragma unroll
    for (int nb = 0; nb < 4; nb++)
        #pragma unroll
        for (int q = 0; q < 4; q++) c[nb][q] = 0.f;

    const int rA = warp * 8 + (lane >> 2);
    const int kc = 2 * (lane & 3);
    #pragma unroll
    for (int kb = 0; kb < 8; kb++) {
        const unsigned aH0 = *(const unsigned*)&hH[rA][kb * 16 + kc];
        const unsigned aH4 = *(const unsigned*)&hH[rA][kb * 16 + kc + 8];
        #pragma unroll
        for (int nb = 0; nb < 4; nb++) {
            const uint2 bH = g_w2fH[kb][nb][lane];
            const uint2 bL = g_w2fL[kb][nb][lane];
            mma16816(c[nb], aH0, aH0, aH4, aH4, bH.x, bH.y);  // h * w_hi
            mma16816(c[nb], aH0, aH0, aH4, aH4, bL.x, bL.y);  // h * w_lo
        }
    }
    // bias: thread holds o2[r=lane/4][j=nb*8+2*(lane&3)+{0,1}] in c[nb][0..1]
    const int jc = 2 * (lane & 3);
    #pragma unroll
    for (int nb = 0; nb < 4; nb++) {
        const float2 bb = *(const float2*)&g_b2s[nb * 8 + jc];
        c[nb][0] += bb.x; c[nb][1] += bb.y;
    }

    // ---- layer 3: A frags built in-register from c via CReLU (hi/lo split) ----
    float d[4][4];
    #pragma unroll
    for (int nb = 0; nb < 4; nb++)
        #pragma unroll
        for (int q = 0; q < 4; q++) d[nb][q] = 0.f;

    #pragma unroll
    for (int kb2 = 0; kb2 < 4; kb2++) {
        const int s0 = (kb2 & 1) * 2, s1 = s0 + 1;
        const float sg = (kb2 < 2) ? 1.f : -1.f;
        const float p0 = fmaxf(sg * c[s0][0], 0.f), p1 = fmaxf(sg * c[s0][1], 0.f);
        const float q0 = fmaxf(sg * c[s1][0], 0.f), q1 = fmaxf(sg * c[s1][1], 0.f);
        unsigned aH0, aL0, aH4, aL4;
        split2(p0, p1, aH0, aL0);
        split2(q0, q1, aH4, aL4);
        #pragma unroll
        for (int nb = 0; nb < 4; nb++) {
            const uint2 b = g_w3f[kb2][nb][lane];
            mma16816(d[nb], aH0, aH0, aH4, aH4, b.x, b.y);
            mma16816(d[nb], aL0, aL0, aL4, aL4, b.x, b.y);
        }
    }

    // ---- layer 4: CReLU dot + quad reduction ----
    float g = 0.f;
    #pragma unroll
    for (int nb = 0; nb < 4; nb++) {
        const float2 b3p = *(const float2*)&g_b3s[nb * 8 + jc];
        const float2 w4p = *(const float2*)&g_w4s[nb * 8 + jc];
        const float2 w4n = *(const float2*)&g_w4s[32 + nb * 8 + jc];
        const float oa = d[nb][0] + b3p.x;
        const float ob = d[nb][1] + b3p.y;
        g += fmaxf(oa, 0.f) * w4p.x + fmaxf(-oa, 0.f) * w4n.x;
        g += fmaxf(ob, 0.f) * w4p.y + fmaxf(-ob, 0.f) * w4n.y;
    }
    g += __shfl_xor_sync(FULLMASK, g, 1);
    g += __shfl_xor_sync(FULLMASK, g, 2);
    if ((lane & 3) == 0) {
        const int row = row0 + (lane >> 2);
        if (row < nrows) out[row] = g;
    }
}

extern "C" void kernel_launch(void* const* d_in, const int* in_sizes, int n_in,
                              void* d_out, int out_size)
{
    const int*   x   = (const int*)  d_in[0];
    const float* emb = (const float*)d_in[1];
    const float* w2  = (const float*)d_in[2];
    const float* b2  = (const float*)d_in[3];
    const float* w3  = (const float*)d_in[4];
    const float* b3  = (const float*)d_in[5];
    const float* w4  = (const float*)d_in[6];
    float* out = (float*)d_out;

    convert_emb_kernel<<<(VOCAB * EMBD / 8 + 255) / 256, 256>>>(emb, w2, b2, w3, b3, w4);

    const int nrows  = in_sizes[0] / 32;
    const int blocks = (nrows + ROWS_PER_BLOCK - 1) / ROWS_PER_BLOCK;
    silk_nnue_kernel<<<blocks, 256>>>(x, out, nrows);
}